// round 14
// baseline (speedup 1.0000x reference)
#include <cuda_runtime.h>
#include <cuda_fp16.h>
#include <cstdint>

// ---------------------------------------------------------------------------
// Problem constants
// ---------------------------------------------------------------------------
#define NB      8
#define LQN     2500
#define NHD     8
#define NLV     4
#define NPT     8
#define NZP     4
#define LEN_IN  14960
#define MVAL    (NB * LEN_IN)   // 119680 = 935*128
#define MQ      (NB * LQN)      // 20000

#define VAL_CTAS  (2 * (MVAL / 128))          // 1870
#define QOUT_CTAS (6 * ((MQ + 127) / 128))    // 942

// value tensor copies: copyA pairs (even,odd) tokens; copyB shifts by one token
#define COPYB_HALFS ((size_t)MVAL * 256)      // 30,638,080 halves
#define COPYB_BYTES 61276160u                  // MVAL*256*2 bytes

// ---------------------------------------------------------------------------
// Scratch (static device globals)
// ---------------------------------------------------------------------------
__device__ __align__(256) __half g_WvT[256 * 256];             // [n][k] fp16
__device__ __align__(256) __half g_WqT[768 * 256];             // Wo|Wa fused, [n][k] fp16
__device__ __align__(256) float  g_bq[768];                    // bo|ba fused
__device__ __align__(256) __half g_valueh[2 * (size_t)MVAL * 256]; // dual-copy head-major
__device__ __align__(256) float  g_qout[(size_t)MQ * 768];     // cols 0-511 off, 512-767 aw

// ---------------------------------------------------------------------------
// PTX helpers (baseline PTX only)
// ---------------------------------------------------------------------------
__device__ __forceinline__ uint32_t smem_u32(const void* p) {
    uint32_t a;
    asm("{ .reg .u64 t; cvta.to.shared.u64 t, %1; cvt.u32.u64 %0, t; }" : "=r"(a) : "l"(p));
    return a;
}
__device__ __forceinline__ void cp16(uint32_t dst, const void* src) {
    asm volatile("cp.async.cg.shared.global [%0], [%1], 16;"
                 :: "r"(dst), "l"(src) : "memory");
}
__device__ __forceinline__ void cp_commit() { asm volatile("cp.async.commit_group;" ::: "memory"); }
__device__ __forceinline__ void cp_wait1()  { asm volatile("cp.async.wait_group 1;" ::: "memory"); }
__device__ __forceinline__ void cp_wait0()  { asm volatile("cp.async.wait_group 0;" ::: "memory"); }

__device__ __forceinline__ void ldm_x4(uint32_t r[4], uint32_t addr) {
    asm volatile("ldmatrix.sync.aligned.m8n8.x4.shared.b16 {%0,%1,%2,%3}, [%4];"
                 : "=r"(r[0]), "=r"(r[1]), "=r"(r[2]), "=r"(r[3]) : "r"(addr));
}
__device__ __forceinline__ void mma16816(float c[4], const uint32_t a[4], const uint32_t b[2]) {
    asm volatile(
        "mma.sync.aligned.m16n8k16.row.col.f32.f16.f16.f32 "
        "{%0,%1,%2,%3}, {%4,%5,%6,%7}, {%8,%9}, {%0,%1,%2,%3};"
        : "+f"(c[0]), "+f"(c[1]), "+f"(c[2]), "+f"(c[3])
        : "r"(a[0]), "r"(a[1]), "r"(a[2]), "r"(a[3]), "r"(b[0]), "r"(b[1]));
}
__device__ __forceinline__ uint32_t pack2h(float x, float y) {
    __half2 h = __floats2half2_rn(x, y);
    return *(const uint32_t*)&h;
}

// ---------------------------------------------------------------------------
// Weight prep: coalesced 32x32 SMEM tile transpose + fp16 convert.
// Blocks 0..63: Wv tiles; 64..255: Wq (Wo|Wa) tiles; 256: bias concat.
// ---------------------------------------------------------------------------
__global__ __launch_bounds__(256) void prep_w(
    const float* __restrict__ Wv, const float* __restrict__ Wo,
    const float* __restrict__ Wa, const float* __restrict__ bo,
    const float* __restrict__ ba, __half* __restrict__ WvT,
    __half* __restrict__ WqT, float* __restrict__ bq)
{
    __shared__ float t[32][33];
    const int b = blockIdx.x;
    const int tx = threadIdx.x & 31, ty = threadIdx.x >> 5;

    if (b < 64 + 192) {
        const bool isV = (b < 64);
        const int tb = isV ? b : b - 64;
        const int tn_n = isV ? 8 : 24;
        const int tk = tb / tn_n, tn = tb % tn_n;

        #pragma unroll
        for (int i = 0; i < 4; i++) {
            const int k = tk * 32 + ty + 8 * i;
            const int nn = tn * 32 + tx;
            float v;
            if (isV) v = Wv[k * 256 + nn];
            else     v = (nn < 512) ? Wo[k * 512 + nn] : Wa[k * 256 + (nn - 512)];
            t[ty + 8 * i][tx] = v;
        }
        __syncthreads();
        #pragma unroll
        for (int i = 0; i < 4; i++) {
            const int nn = tn * 32 + ty + 8 * i;
            const int k  = tk * 32 + tx;
            const __half hv = __float2half(t[tx][ty + 8 * i]);
            if (isV) WvT[nn * 256 + k] = hv;
            else     WqT[nn * 256 + k] = hv;
        }
    } else {
        for (int i = threadIdx.x; i < 768; i += 256)
            bq[i] = (i < 512) ? bo[i] : ba[i - 512];
    }
}

// ---------------------------------------------------------------------------
// FP16 tensor-core GEMM body (fused fp32->fp16 A conversion):
//   C tile (br,bc) of fp16(A[M,256]) @ BT[N,256]^T + bias[N]
// VOUT=true: fp16 head-major value output, dual-copy (A + token-shifted B).
// ---------------------------------------------------------------------------
#define ROWB 80                      // bytes per 32-half SMEM row
#define TILEB (128 * ROWB)           // 10240
#define BUFB  (2 * TILEB)            // A + B per stage

template<bool VOUT>
__device__ __forceinline__ void gemm_body(
    unsigned char* sm,
    const float* __restrict__ A, const __half* __restrict__ BT,
    const float* __restrict__ bias, float* __restrict__ Cf, __half* __restrict__ Ch,
    int M, int N, int bc, int br)
{
    const uint32_t smb = smem_u32(sm);
    const int tid = threadIdx.x;
    const int lane = tid & 31, wid = tid >> 5;
    const int gid = lane >> 2, tig = lane & 3;
    const int wm = (wid >> 1) * 32, wn = (wid & 1) * 64;

    const int r0 = tid >> 2, k0 = tid & 3;
    const int gr0 = br * 128 + r0, gr1 = gr0 + 64;
    const int gr0c = (gr0 < M) ? gr0 : (M - 1);
    const int gr1c = (gr1 < M) ? gr1 : (M - 1);
    const float* aP0 = A + (size_t)gr0c * 256 + k0 * 8;
    const float* aP1 = A + (size_t)gr1c * 256 + k0 * 8;
    const __half* bP0 = BT + (size_t)(bc * 128 + r0) * 256 + k0 * 8;
    const __half* bP1 = BT + (size_t)(bc * 128 + r0 + 64) * 256 + k0 * 8;
    const uint32_t offA0 = r0 * ROWB + k0 * 16;
    const uint32_t offA1 = (r0 + 64) * ROWB + k0 * 16;

    float c[2][8][4];
    #pragma unroll
    for (int mi = 0; mi < 2; mi++)
        #pragma unroll
        for (int nj = 0; nj < 8; nj++)
            #pragma unroll
            for (int q = 0; q < 4; q++) c[mi][nj][q] = 0.f;

    float ar[2][8];

    auto ldgA = [&](int kt) {
        #pragma unroll
        for (int cch = 0; cch < 2; cch++) {
            const float* src = (cch ? aP1 : aP0) + kt * 32;
            float4 v0 = *(const float4*)src;
            float4 v1 = *(const float4*)(src + 4);
            ar[cch][0] = v0.x; ar[cch][1] = v0.y; ar[cch][2] = v0.z; ar[cch][3] = v0.w;
            ar[cch][4] = v1.x; ar[cch][5] = v1.y; ar[cch][6] = v1.z; ar[cch][7] = v1.w;
        }
    };
    auto stsA = [&](int buf) {
        unsigned char* base = sm + buf * BUFB;
        #pragma unroll
        for (int cch = 0; cch < 2; cch++) {
            uint4 u;
            u.x = pack2h(ar[cch][0], ar[cch][1]);
            u.y = pack2h(ar[cch][2], ar[cch][3]);
            u.z = pack2h(ar[cch][4], ar[cch][5]);
            u.w = pack2h(ar[cch][6], ar[cch][7]);
            *(uint4*)(base + (cch ? offA1 : offA0)) = u;
        }
    };
    auto bcp = [&](int kt, int buf) {
        const uint32_t bs = smb + buf * BUFB + TILEB;
        cp16(bs + offA0, bP0 + kt * 32);
        cp16(bs + offA1, bP1 + kt * 32);
        cp_commit();
    };

    ldgA(0); stsA(0); bcp(0, 0);
    ldgA(1);

    #pragma unroll 1
    for (int kt = 0; kt < 8; kt++) {
        const int cur = kt & 1, nxt = cur ^ 1;
        if (kt < 7) { stsA(nxt); bcp(kt + 1, nxt); }
        if (kt < 6) { ldgA(kt + 2); }
        if (kt < 7) cp_wait1(); else cp_wait0();
        __syncthreads();

        const uint32_t asB = smb + cur * BUFB;
        const uint32_t bsB = asB + TILEB;

        #pragma unroll
        for (int ks = 0; ks < 32; ks += 16) {
            const int kc0 = ks >> 3;
            uint32_t a[2][4], b[8][2];
            #pragma unroll
            for (int mi = 0; mi < 2; mi++) {
                const int row = wm + mi * 16 + (lane & 15);
                ldm_x4(a[mi], asB + row * ROWB + (kc0 + (lane >> 4)) * 16);
            }
            #pragma unroll
            for (int njp = 0; njp < 4; njp++) {
                const int row = wn + njp * 16 + ((lane >> 4) << 3) + (lane & 7);
                uint32_t t[4];
                ldm_x4(t, bsB + row * ROWB + (kc0 + ((lane >> 3) & 1)) * 16);
                b[2 * njp][0] = t[0]; b[2 * njp][1] = t[1];
                b[2 * njp + 1][0] = t[2]; b[2 * njp + 1][1] = t[3];
            }
            #pragma unroll
            for (int mi = 0; mi < 2; mi++)
                #pragma unroll
                for (int nj = 0; nj < 8; nj++)
                    mma16816(c[mi][nj], a[mi], b[nj]);
        }
        __syncthreads();
    }

    #pragma unroll
    for (int mi = 0; mi < 2; mi++) {
        const int rbase = br * 128 + wm + mi * 16 + gid;
        #pragma unroll
        for (int hh = 0; hh < 2; hh++) {
            const int row = rbase + hh * 8;
            if (row >= M) continue;
            if (VOUT) {
                const int n = row / LEN_IN, tok = row - n * LEN_IN;
                #pragma unroll
                for (int nj = 0; nj < 8; nj++) {
                    const int col = bc * 128 + wn + nj * 8 + tig * 2;
                    const float2 bb = *(const float2*)(bias + col);
                    __half2 hv = __floats2half2_rn(c[mi][nj][2 * hh] + bb.x,
                                                   c[mi][nj][2 * hh + 1] + bb.y);
                    const int h = col >> 5, ch = col & 31;
                    __half* pA = Ch + (((size_t)(n * 8 + h) * LEN_IN + tok) * 32 + ch);
                    *(__half2*)pA = hv;
                    if (tok > 0)
                        *(__half2*)(pA + (COPYB_HALFS - 32)) = hv;  // copyB slot tok-1
                }
            } else {
                #pragma unroll
                for (int nj = 0; nj < 8; nj++) {
                    const int col = bc * 128 + wn + nj * 8 + tig * 2;
                    const float2 bb = *(const float2*)(bias + col);
                    float2 o = make_float2(c[mi][nj][2 * hh] + bb.x,
                                           c[mi][nj][2 * hh + 1] + bb.y);
                    *(float2*)(Cf + (size_t)row * N + col) = o;
                }
            }
        }
    }
}

// Merged launch: first VAL_CTAS blocks do the value GEMM, the rest do off|aw.
__global__ __launch_bounds__(256) void gemm_both(
    const float* __restrict__ inflat, const __half* __restrict__ WvT,
    const float* __restrict__ bv, __half* __restrict__ valh,
    const float* __restrict__ query, const __half* __restrict__ WqT,
    const float* __restrict__ bq, float* __restrict__ qout)
{
    __shared__ __align__(16) unsigned char sm[2 * BUFB];
    const int cta = blockIdx.x;
    if (cta < VAL_CTAS) {
        gemm_body<true>(sm, inflat, WvT, bv, nullptr, valh,
                        MVAL, 256, cta & 1, cta >> 1);
    } else {
        const int c2 = cta - VAL_CTAS;
        gemm_body<false>(sm, query, WqT, bq, qout, nullptr,
                         MQ, 768, c2 % 6, c2 / 6);
    }
}

// ---------------------------------------------------------------------------
// Fused softmax + deformable bilinear sampling + aggregation.
// One warp per (n,q,h).
// Phase 1 (lane = point): softmax + tap prep -> sdata[point] =
//   int4{ boff_row0, w01_row0, boff_row1, w01_row1 }. boff selects copyA/B so
//   every 2-token span is ONE 128B-aligned L1 line.
// Phase 2 (lane = p3|c): per (point-group, row) one LDG.128 covers 4 spans,
//   each exactly one line. Slot weight via byte_perm; 2-tap fp16 chains,
//   fp32 flush per group; shfl-xor reduction.
// ---------------------------------------------------------------------------
__global__ __launch_bounds__(256) void msda_sample(
    const float* __restrict__ ref,       // (N, LQ, NZ, 2)
    const int*   __restrict__ spatial,   // (NL, 2)
    const int*   __restrict__ lsi,       // (NL,)
    float*       __restrict__ out)       // (N, LQ, 256)
{
    __shared__ int4 sdata[8][32];        // [warp][point]

    const int lane = threadIdx.x & 31;
    const int wid  = threadIdx.x >> 5;
    const int gw   = blockIdx.x * 8 + wid;
    const int h    = gw & 7;
    const int nq   = gw >> 3;

    // ---- phase 1: lane = point (l*8+p) ----
    {
        const int l = lane >> 3, p = lane & 7;
        const int hl = spatial[2 * l], wl = spatial[2 * l + 1];
        const int start = lsi[l];

        const float2 offv = *(const float2*)(g_qout + (size_t)nq * 768 + (h * 4 + l) * 16 + p * 2);
        const int z = p & 3;
        const float2 rp = *(const float2*)(ref + ((size_t)nq * NZP + z) * 2);
        const float x = (rp.x + offv.x / (float)wl) * (float)wl - 0.5f;
        const float y = (rp.y + offv.y / (float)hl) * (float)hl - 0.5f;
        const float x0f = floorf(x), y0f = floorf(y);
        const float fx = x - x0f, fy = y - y0f;
        const int x0 = (int)x0f, y0 = (int)y0f;

        // warp softmax over the 32 logits
        float a = g_qout[(size_t)nq * 768 + 512 + h * 32 + lane];
        float m = a;
        #pragma unroll
        for (int s = 16; s; s >>= 1) m = fmaxf(m, __shfl_xor_sync(0xffffffffu, m, s));
        float e = __expf(a - m);
        float ssum = e;
        #pragma unroll
        for (int s = 16; s; s >>= 1) ssum += __shfl_xor_sync(0xffffffffu, ssum, s);
        const float awn = e / ssum;

        const int bx = min(max(x0, 0), wl - 2);
        const int u0 = bx - x0;
        const float wx0 = (u0 == 0) ? (1.f - fx) : ((u0 == 1) ? fx : 0.f);
        const float wx1 = (u0 + 1 == 0) ? (1.f - fx) : ((u0 + 1 == 1) ? fx : 0.f);

        uint32_t boffs[2], wws[2];
        #pragma unroll
        for (int ry = 0; ry < 2; ry++) {
            const int yi = y0 + ry;
            const bool vy = (yi >= 0) && (yi < hl);
            const int yc = min(max(yi, 0), hl - 1);
            const float wy = (ry ? fy : 1.f - fy) * (vy ? awn : 0.f);
            const int idx = start + yc * wl + bx;
            const int par = idx & 1;
            boffs[ry] = (uint32_t)(idx - par) * 64u + (par ? COPYB_BYTES : 0u);
            wws[ry]   = pack2h(wx0 * wy, wx1 * wy);
        }
        sdata[wid][lane] = make_int4((int)boffs[0], (int)wws[0],
                                     (int)boffs[1], (int)wws[1]);
    }
    __syncwarp();

    // ---- phase 2: lane = p3 (lane>>3) | c (lane&7: 16B chunk of 128B span) ----
    const int n  = nq / LQN;
    const int p3 = lane >> 3;              // point within group of 4
    const int c  = lane & 7;               // chunk within 2-token span
    const uint32_t wsel = (c & 4) ? 0x3232u : 0x1010u;  // replicate hi/lo half
    const char* vbytes = (const char*)g_valueh
                       + ((size_t)(n * 8 + h)) * (LEN_IN * 64) + c * 16;

    float acc[8];
    #pragma unroll
    for (int i = 0; i < 8; i++) acc[i] = 0.f;

    #pragma unroll
    for (int g = 0; g < 8; g++) {
        const int4 sd = sdata[wid][g * 4 + p3];
        const uint32_t wa_u = __byte_perm((uint32_t)sd.y, 0u, wsel);
        const __half2 wa = *(const __half2*)&wa_u;
        const uint4 va = *(const uint4*)(vbytes + (uint32_t)sd.x);
        const uint32_t wb_u = __byte_perm((uint32_t)sd.w, 0u, wsel);
        const __half2 wb = *(const __half2*)&wb_u;
        const uint4 vb = *(const uint4*)(vbytes + (uint32_t)sd.z);

        __half2 hacc[4];
        hacc[0] = __hmul2(*(const __half2*)&va.x, wa);
        hacc[1] = __hmul2(*(const __half2*)&va.y, wa);
        hacc[2] = __hmul2(*(const __half2*)&va.z, wa);
        hacc[3] = __hmul2(*(const __half2*)&va.w, wa);
        hacc[0] = __hfma2(*(const __half2*)&vb.x, wb, hacc[0]);
        hacc[1] = __hfma2(*(const __half2*)&vb.y, wb, hacc[1]);
        hacc[2] = __hfma2(*(const __half2*)&vb.z, wb, hacc[2]);
        hacc[3] = __hfma2(*(const __half2*)&vb.w, wb, hacc[3]);

        #pragma unroll
        for (int i = 0; i < 4; i++) {
            const float2 f = __half22float2(hacc[i]);
            acc[2 * i]     += f.x;
            acc[2 * i + 1] += f.y;
        }
    }

    // reduce over bit2 (span half pairing via c) and p3 (bits 3-4)
    #pragma unroll
    for (int st = 16; st >= 4; st >>= 1) {
        #pragma unroll
        for (int i = 0; i < 8; i++)
            acc[i] += __shfl_xor_sync(0xffffffffu, acc[i], st);
    }
    if (lane < 4) {
        float* base = out + (size_t)nq * 256 + h * 32 + lane * 8;
        *(float4*)base       = make_float4(acc[0], acc[1], acc[2], acc[3]);
        *(float4*)(base + 4) = make_float4(acc[4], acc[5], acc[6], acc[7]);
    }
}

// ---------------------------------------------------------------------------
// Launch
// ---------------------------------------------------------------------------
extern "C" void kernel_launch(void* const* d_in, const int* in_sizes, int n_in,
                              void* d_out, int out_size)
{
    const float* query   = (const float*)d_in[0];
    // d_in[1] = query_pos (unused by the reference forward)
    const float* refpts  = (const float*)d_in[2];
    const float* inflat  = (const float*)d_in[3];
    const int*   spatial = (const int*)d_in[4];
    const int*   lsi     = (const int*)d_in[5];
    const float* Wv      = (const float*)d_in[6];
    const float* bv      = (const float*)d_in[7];
    const float* Wo      = (const float*)d_in[8];
    const float* bo      = (const float*)d_in[9];
    const float* Wa      = (const float*)d_in[10];
    const float* ba      = (const float*)d_in[11];
    float*       out     = (float*)d_out;

    __half *pWvT, *pWqT, *pvalh;
    float *pbq, *pqout;
    cudaGetSymbolAddress((void**)&pWvT,  g_WvT);
    cudaGetSymbolAddress((void**)&pWqT,  g_WqT);
    cudaGetSymbolAddress((void**)&pbq,   g_bq);
    cudaGetSymbolAddress((void**)&pvalh, g_valueh);
    cudaGetSymbolAddress((void**)&pqout, g_qout);

    // 0) weight prep (coalesced tiled transpose + bias concat)
    prep_w<<<257, 256>>>(Wv, Wo, Wa, bo, ba, pWvT, pWqT, pbq);

    // 1+2) merged GEMMs: value (fp16 head-major dual-copy) + off|aw (fp32)
    gemm_both<<<VAL_CTAS + QOUT_CTAS, 256>>>(inflat, pWvT, bv, pvalh,
                                             query, pWqT, pbq, pqout);

    // 3) softmax + deformable sampling + aggregation
    msda_sample<<<(MQ * NHD) / 8, 256>>>(refpts, spatial, lsi, out);
}

// round 15
// speedup vs baseline: 1.1047x; 1.1047x over previous
#include <cuda_runtime.h>
#include <cuda_fp16.h>
#include <cstdint>

// ---------------------------------------------------------------------------
// Problem constants
// ---------------------------------------------------------------------------
#define NB      8
#define LQN     2500
#define NHD     8
#define NLV     4
#define NPT     8
#define NZP     4
#define LEN_IN  14960
#define MVAL    (NB * LEN_IN)   // 119680 = 935*128
#define MQ      (NB * LQN)      // 20000

#define VAL_CTAS  (2 * (MVAL / 128))          // 1870
#define QOUT_CTAS (6 * ((MQ + 127) / 128))    // 942

// ---------------------------------------------------------------------------
// Scratch (static device globals)
// ---------------------------------------------------------------------------
__device__ __align__(256) __half g_WvT[256 * 256];             // [n][k] fp16
__device__ __align__(256) __half g_WqT[768 * 256];             // Wo|Wa fused, [n][k] fp16
__device__ __align__(256) float  g_bq[768];                    // bo|ba fused
__device__ __align__(256) __half g_valueh[(size_t)MVAL * 256]; // head-major (n,h,token,32)
__device__ __align__(256) float  g_qout[(size_t)MQ * 768];     // cols 0-511 off, 512-767 aw

// ---------------------------------------------------------------------------
// PTX helpers (baseline PTX only)
// ---------------------------------------------------------------------------
__device__ __forceinline__ uint32_t smem_u32(const void* p) {
    uint32_t a;
    asm("{ .reg .u64 t; cvta.to.shared.u64 t, %1; cvt.u32.u64 %0, t; }" : "=r"(a) : "l"(p));
    return a;
}
__device__ __forceinline__ void cp16(uint32_t dst, const void* src) {
    asm volatile("cp.async.cg.shared.global [%0], [%1], 16;"
                 :: "r"(dst), "l"(src) : "memory");
}
__device__ __forceinline__ void cp_commit() { asm volatile("cp.async.commit_group;" ::: "memory"); }
__device__ __forceinline__ void cp_wait1()  { asm volatile("cp.async.wait_group 1;" ::: "memory"); }
__device__ __forceinline__ void cp_wait0()  { asm volatile("cp.async.wait_group 0;" ::: "memory"); }

__device__ __forceinline__ void ldm_x4(uint32_t r[4], uint32_t addr) {
    asm volatile("ldmatrix.sync.aligned.m8n8.x4.shared.b16 {%0,%1,%2,%3}, [%4];"
                 : "=r"(r[0]), "=r"(r[1]), "=r"(r[2]), "=r"(r[3]) : "r"(addr));
}
__device__ __forceinline__ void mma16816(float c[4], const uint32_t a[4], const uint32_t b[2]) {
    asm volatile(
        "mma.sync.aligned.m16n8k16.row.col.f32.f16.f16.f32 "
        "{%0,%1,%2,%3}, {%4,%5,%6,%7}, {%8,%9}, {%0,%1,%2,%3};"
        : "+f"(c[0]), "+f"(c[1]), "+f"(c[2]), "+f"(c[3])
        : "r"(a[0]), "r"(a[1]), "r"(a[2]), "r"(a[3]), "r"(b[0]), "r"(b[1]));
}
__device__ __forceinline__ uint32_t pack2h(float x, float y) {
    __half2 h = __floats2half2_rn(x, y);
    return *(const uint32_t*)&h;
}

// ---------------------------------------------------------------------------
// Fused weight prep (R12 flat version): WvT[n][k], WqT = (Wo|Wa)[n][k], bq
// ---------------------------------------------------------------------------
__global__ void prep_w(const float* __restrict__ Wv, const float* __restrict__ Wo,
                       const float* __restrict__ Wa, const float* __restrict__ bo,
                       const float* __restrict__ ba, __half* __restrict__ WvT,
                       __half* __restrict__ WqT, float* __restrict__ bq)
{
    int idx = blockIdx.x * blockDim.x + threadIdx.x;
    if (idx < 65536) {
        int n = idx >> 8, k = idx & 255;
        WvT[idx] = __float2half(Wv[k * 256 + n]);
    } else if (idx < 65536 + 196608) {
        int j = idx - 65536;
        int n = j >> 8, k = j & 255;
        WqT[j] = __float2half((n < 512) ? Wo[k * 512 + n] : Wa[k * 256 + (n - 512)]);
    } else if (idx < 65536 + 196608 + 768) {
        int t = idx - 65536 - 196608;
        bq[t] = (t < 512) ? bo[t] : ba[t - 512];
    }
}

// ---------------------------------------------------------------------------
// FP16 tensor-core GEMM body (fused fp32->fp16 A conversion):
//   C tile (br,bc) of fp16(A[M,256]) @ BT[N,256]^T + bias[N]
// VOUT=true: fp16 head-major value output via SMEM-staged transpose:
//   frags -> SMEM (token stride 80B, conflict-free STS) -> coalesced 16B
//   GMEM stores (contiguous per-head runs). Kills the 2x scattered-store tax.
// ---------------------------------------------------------------------------
#define ROWB 80                      // bytes per 32-half SMEM row
#define TILEB (128 * ROWB)           // 10240
#define BUFB  (2 * TILEB)            // A + B per stage
#define TOKB  80                     // epilogue: bytes per token row (64 data + 16 pad)
#define HEADB (128 * TOKB)           // 10240 per head slab

template<bool VOUT>
__device__ __forceinline__ void gemm_body(
    unsigned char* sm,
    const float* __restrict__ A, const __half* __restrict__ BT,
    const float* __restrict__ bias, float* __restrict__ Cf, __half* __restrict__ Ch,
    int M, int N, int bc, int br)
{
    const uint32_t smb = smem_u32(sm);
    const int tid = threadIdx.x;
    const int lane = tid & 31, wid = tid >> 5;
    const int gid = lane >> 2, tig = lane & 3;
    const int wm = (wid >> 1) * 32, wn = (wid & 1) * 64;

    const int r0 = tid >> 2, k0 = tid & 3;
    const int gr0 = br * 128 + r0, gr1 = gr0 + 64;
    const int gr0c = (gr0 < M) ? gr0 : (M - 1);
    const int gr1c = (gr1 < M) ? gr1 : (M - 1);
    const float* aP0 = A + (size_t)gr0c * 256 + k0 * 8;
    const float* aP1 = A + (size_t)gr1c * 256 + k0 * 8;
    const __half* bP0 = BT + (size_t)(bc * 128 + r0) * 256 + k0 * 8;
    const __half* bP1 = BT + (size_t)(bc * 128 + r0 + 64) * 256 + k0 * 8;
    const uint32_t offA0 = r0 * ROWB + k0 * 16;
    const uint32_t offA1 = (r0 + 64) * ROWB + k0 * 16;

    float c[2][8][4];
    #pragma unroll
    for (int mi = 0; mi < 2; mi++)
        #pragma unroll
        for (int nj = 0; nj < 8; nj++)
            #pragma unroll
            for (int q = 0; q < 4; q++) c[mi][nj][q] = 0.f;

    float ar[2][8];

    auto ldgA = [&](int kt) {
        #pragma unroll
        for (int cch = 0; cch < 2; cch++) {
            const float* src = (cch ? aP1 : aP0) + kt * 32;
            float4 v0 = *(const float4*)src;
            float4 v1 = *(const float4*)(src + 4);
            ar[cch][0] = v0.x; ar[cch][1] = v0.y; ar[cch][2] = v0.z; ar[cch][3] = v0.w;
            ar[cch][4] = v1.x; ar[cch][5] = v1.y; ar[cch][6] = v1.z; ar[cch][7] = v1.w;
        }
    };
    auto stsA = [&](int buf) {
        unsigned char* base = sm + buf * BUFB;
        #pragma unroll
        for (int cch = 0; cch < 2; cch++) {
            uint4 u;
            u.x = pack2h(ar[cch][0], ar[cch][1]);
            u.y = pack2h(ar[cch][2], ar[cch][3]);
            u.z = pack2h(ar[cch][4], ar[cch][5]);
            u.w = pack2h(ar[cch][6], ar[cch][7]);
            *(uint4*)(base + (cch ? offA1 : offA0)) = u;
        }
    };
    auto bcp = [&](int kt, int buf) {
        const uint32_t bs = smb + buf * BUFB + TILEB;
        cp16(bs + offA0, bP0 + kt * 32);
        cp16(bs + offA1, bP1 + kt * 32);
        cp_commit();
    };

    ldgA(0); stsA(0); bcp(0, 0);
    ldgA(1);

    #pragma unroll 1
    for (int kt = 0; kt < 8; kt++) {
        const int cur = kt & 1, nxt = cur ^ 1;
        if (kt < 7) { stsA(nxt); bcp(kt + 1, nxt); }
        if (kt < 6) { ldgA(kt + 2); }
        if (kt < 7) cp_wait1(); else cp_wait0();
        __syncthreads();

        const uint32_t asB = smb + cur * BUFB;
        const uint32_t bsB = asB + TILEB;

        #pragma unroll
        for (int ks = 0; ks < 32; ks += 16) {
            const int kc0 = ks >> 3;
            uint32_t a[2][4], b[8][2];
            #pragma unroll
            for (int mi = 0; mi < 2; mi++) {
                const int row = wm + mi * 16 + (lane & 15);
                ldm_x4(a[mi], asB + row * ROWB + (kc0 + (lane >> 4)) * 16);
            }
            #pragma unroll
            for (int njp = 0; njp < 4; njp++) {
                const int row = wn + njp * 16 + ((lane >> 4) << 3) + (lane & 7);
                uint32_t t[4];
                ldm_x4(t, bsB + row * ROWB + (kc0 + ((lane >> 3) & 1)) * 16);
                b[2 * njp][0] = t[0]; b[2 * njp][1] = t[1];
                b[2 * njp + 1][0] = t[2]; b[2 * njp + 1][1] = t[3];
            }
            #pragma unroll
            for (int mi = 0; mi < 2; mi++)
                #pragma unroll
                for (int nj = 0; nj < 8; nj++)
                    mma16816(c[mi][nj], a[mi], b[nj]);
        }
        __syncthreads();
    }

    if (VOUT) {
        // ---- staged epilogue: frags -> SMEM (head-major, 80B token stride) ----
        // M = MVAL is divisible by 128: no row guards needed.
        #pragma unroll
        for (int mi = 0; mi < 2; mi++) {
            #pragma unroll
            for (int hh = 0; hh < 2; hh++) {
                const int tok = wm + mi * 16 + gid + 8 * hh;
                #pragma unroll
                for (int nj = 0; nj < 8; nj++) {
                    const int cc = wn + nj * 8 + tig * 2;      // 0..127 within tile
                    const float2 bb = *(const float2*)(bias + bc * 128 + cc);
                    __half2 hv = __floats2half2_rn(c[mi][nj][2 * hh] + bb.x,
                                                   c[mi][nj][2 * hh + 1] + bb.y);
                    const int hl = cc >> 5, ch = cc & 31;
                    *(__half2*)(sm + hl * HEADB + tok * TOKB + ch * 2) = hv;
                }
            }
        }
        __syncthreads();
        // ---- SMEM -> GMEM, coalesced 16B chunks (contiguous runs per head) ----
        #pragma unroll
        for (int i = 0; i < 8; i++) {
            const int g = i * 256 + tid;            // 0..2047 chunks of 16B
            const int hl = g >> 9, rem = g & 511;   // 512 chunks per head
            const int tok = rem >> 2, c4 = rem & 3;
            const int row = br * 128 + tok;
            const int n = row / LEN_IN, tk = row - n * LEN_IN;
            const uint4 v = *(const uint4*)(sm + hl * HEADB + tok * TOKB + c4 * 16);
            *(uint4*)((char*)Ch + (((size_t)(n * 8 + bc * 4 + hl) * LEN_IN + tk) * 64
                                    + c4 * 16)) = v;
        }
    } else {
        #pragma unroll
        for (int mi = 0; mi < 2; mi++) {
            const int rbase = br * 128 + wm + mi * 16 + gid;
            #pragma unroll
            for (int hh = 0; hh < 2; hh++) {
                const int row = rbase + hh * 8;
                if (row >= M) continue;
                #pragma unroll
                for (int nj = 0; nj < 8; nj++) {
                    const int col = bc * 128 + wn + nj * 8 + tig * 2;
                    const float2 bb = *(const float2*)(bias + col);
                    float2 o = make_float2(c[mi][nj][2 * hh] + bb.x,
                                           c[mi][nj][2 * hh + 1] + bb.y);
                    *(float2*)(Cf + (size_t)row * N + col) = o;
                }
            }
        }
    }
}

// Merged launch: first VAL_CTAS blocks do the value GEMM, the rest do off|aw.
__global__ __launch_bounds__(256) void gemm_both(
    const float* __restrict__ inflat, const __half* __restrict__ WvT,
    const float* __restrict__ bv, __half* __restrict__ valh,
    const float* __restrict__ query, const __half* __restrict__ WqT,
    const float* __restrict__ bq, float* __restrict__ qout)
{
    __shared__ __align__(16) unsigned char sm[2 * BUFB];   // 40960 B; reused by epilogue
    const int cta = blockIdx.x;
    if (cta < VAL_CTAS) {
        gemm_body<true>(sm, inflat, WvT, bv, nullptr, valh,
                        MVAL, 256, cta & 1, cta >> 1);
    } else {
        const int c2 = cta - VAL_CTAS;
        gemm_body<false>(sm, query, WqT, bq, qout, nullptr,
                         MQ, 768, c2 % 6, c2 / 6);
    }
}

// ---------------------------------------------------------------------------
// Fused softmax + deformable bilinear sampling + aggregation (R12 version).
// One warp per (n,q,h). Phase 1: per-point prep -> sdata spans; Phase 2:
// one LDG.128 covers 4 spans (16B chunk per lane), fp16 2-tap chains,
// shfl-xor reduction.
// ---------------------------------------------------------------------------
__global__ __launch_bounds__(256) void msda_sample(
    const float* __restrict__ ref,       // (N, LQ, NZ, 2)
    const int*   __restrict__ spatial,   // (NL, 2)
    const int*   __restrict__ lsi,       // (NL,)
    float*       __restrict__ out)       // (N, LQ, 256)
{
    __shared__ int2 sdata[8][32][2];     // [warp][point][ry] = {byte_off, w01_h2}

    const int lane = threadIdx.x & 31;
    const int wid  = threadIdx.x >> 5;
    const int gw   = blockIdx.x * 8 + wid;
    const int h    = gw & 7;
    const int nq   = gw >> 3;

    // ---- phase 1: lane = point (l*8+p) ----
    {
        const int l = lane >> 3, p = lane & 7;
        const int hl = spatial[2 * l], wl = spatial[2 * l + 1];
        const int start = lsi[l];

        const float2 offv = *(const float2*)(g_qout + (size_t)nq * 768 + (h * 4 + l) * 16 + p * 2);
        const int z = p & 3;
        const float2 rp = *(const float2*)(ref + ((size_t)nq * NZP + z) * 2);
        const float x = (rp.x + offv.x / (float)wl) * (float)wl - 0.5f;
        const float y = (rp.y + offv.y / (float)hl) * (float)hl - 0.5f;
        const float x0f = floorf(x), y0f = floorf(y);
        const float fx = x - x0f, fy = y - y0f;
        const int x0 = (int)x0f, y0 = (int)y0f;

        // warp softmax over the 32 logits
        float a = g_qout[(size_t)nq * 768 + 512 + h * 32 + lane];
        float m = a;
        #pragma unroll
        for (int s = 16; s; s >>= 1) m = fmaxf(m, __shfl_xor_sync(0xffffffffu, m, s));
        float e = __expf(a - m);
        float ssum = e;
        #pragma unroll
        for (int s = 16; s; s >>= 1) ssum += __shfl_xor_sync(0xffffffffu, ssum, s);
        const float awn = e / ssum;

        const int bx = min(max(x0, 0), wl - 2);
        const int u0 = bx - x0;
        const float wx0 = (u0 == 0) ? (1.f - fx) : ((u0 == 1) ? fx : 0.f);
        const float wx1 = (u0 + 1 == 0) ? (1.f - fx) : ((u0 + 1 == 1) ? fx : 0.f);

        #pragma unroll
        for (int ry = 0; ry < 2; ry++) {
            const int yi = y0 + ry;
            const bool vy = (yi >= 0) && (yi < hl);
            const int yc = min(max(yi, 0), hl - 1);
            const float wy = (ry ? fy : 1.f - fy) * (vy ? awn : 0.f);
            sdata[wid][lane][ry] = make_int2((start + yc * wl + bx) * 64,
                                            (int)pack2h(wx0 * wy, wx1 * wy));
        }
    }
    __syncwarp();

    // ---- phase 2: lane = p3 (lane>>3) | c (lane&7: 16B chunk of 128B span) ----
    const int n  = nq / LQN;
    const int p3 = lane >> 3;              // point within group of 4
    const int c  = lane & 7;               // chunk within 2-token span
    const uint32_t wsel = (c & 4) ? 0x3232u : 0x1010u;  // replicate hi/lo half
    const char* vbytes = (const char*)g_valueh
                       + ((size_t)(n * 8 + h)) * (LEN_IN * 64) + c * 16;

    float acc[8];
    #pragma unroll
    for (int i = 0; i < 8; i++) acc[i] = 0.f;

    #pragma unroll
    for (int g = 0; g < 8; g++) {
        __half2 hacc[4];
        #pragma unroll
        for (int r = 0; r < 2; r++) {
            const int2 sd = sdata[wid][g * 4 + p3][r];
            const uint32_t wb_u = __byte_perm((uint32_t)sd.y, 0u, wsel);
            const __half2 wb = *(const __half2*)&wb_u;
            const uint4 v = *(const uint4*)(vbytes + (uint32_t)sd.x);
            if (r == 0) {
                hacc[0] = __hmul2(*(const __half2*)&v.x, wb);
                hacc[1] = __hmul2(*(const __half2*)&v.y, wb);
                hacc[2] = __hmul2(*(const __half2*)&v.z, wb);
                hacc[3] = __hmul2(*(const __half2*)&v.w, wb);
            } else {
                hacc[0] = __hfma2(*(const __half2*)&v.x, wb, hacc[0]);
                hacc[1] = __hfma2(*(const __half2*)&v.y, wb, hacc[1]);
                hacc[2] = __hfma2(*(const __half2*)&v.z, wb, hacc[2]);
                hacc[3] = __hfma2(*(const __half2*)&v.w, wb, hacc[3]);
            }
        }
        #pragma unroll
        for (int i = 0; i < 4; i++) {
            const float2 f = __half22float2(hacc[i]);
            acc[2 * i]     += f.x;
            acc[2 * i + 1] += f.y;
        }
    }

    // reduce over bit2 (span pairing via c) and p3 (bits 3-4)
    #pragma unroll
    for (int st = 16; st >= 4; st >>= 1) {
        #pragma unroll
        for (int i = 0; i < 8; i++)
            acc[i] += __shfl_xor_sync(0xffffffffu, acc[i], st);
    }
    if (lane < 4) {
        float* base = out + (size_t)nq * 256 + h * 32 + lane * 8;
        *(float4*)base       = make_float4(acc[0], acc[1], acc[2], acc[3]);
        *(float4*)(base + 4) = make_float4(acc[4], acc[5], acc[6], acc[7]);
    }
}

// ---------------------------------------------------------------------------
// Launch
// ---------------------------------------------------------------------------
extern "C" void kernel_launch(void* const* d_in, const int* in_sizes, int n_in,
                              void* d_out, int out_size)
{
    const float* query   = (const float*)d_in[0];
    // d_in[1] = query_pos (unused by the reference forward)
    const float* refpts  = (const float*)d_in[2];
    const float* inflat  = (const float*)d_in[3];
    const int*   spatial = (const int*)d_in[4];
    const int*   lsi     = (const int*)d_in[5];
    const float* Wv      = (const float*)d_in[6];
    const float* bv      = (const float*)d_in[7];
    const float* Wo      = (const float*)d_in[8];
    const float* bo      = (const float*)d_in[9];
    const float* Wa      = (const float*)d_in[10];
    const float* ba      = (const float*)d_in[11];
    float*       out     = (float*)d_out;

    __half *pWvT, *pWqT, *pvalh;
    float *pbq, *pqout;
    cudaGetSymbolAddress((void**)&pWvT,  g_WvT);
    cudaGetSymbolAddress((void**)&pWqT,  g_WqT);
    cudaGetSymbolAddress((void**)&pbq,   g_bq);
    cudaGetSymbolAddress((void**)&pvalh, g_valueh);
    cudaGetSymbolAddress((void**)&pqout, g_qout);

    // 0) fused weight prep
    prep_w<<<(65536 + 196608 + 768 + 255) / 256, 256>>>(Wv, Wo, Wa, bo, ba, pWvT, pWqT, pbq);

    // 1+2) merged GEMMs: value (fp16 head-major, staged epilogue) + off|aw (fp32)
    gemm_both<<<VAL_CTAS + QOUT_CTAS, 256>>>(inflat, pWvT, bv, pvalh,
                                             query, pWqT, pbq, pqout);

    // 3) softmax + deformable sampling + aggregation
    msda_sample<<<(MQ * NHD) / 8, 256>>>(refpts, spatial, lsi, out);
}